// round 10
// baseline (speedup 1.0000x reference)
#include <cuda_runtime.h>
#include <math.h>
#include <stdint.h>

#define G_   4
#define HW   4096
#define N_   32
#define TH   16
#define TW   16
#define HALO 3
#define SH   22
#define SW   22
#define PSTR 20
#define THREADS 128
#define PPT  2

// smem layout (bytes)
#define SWC_U64   1728                 // conv weights [pos][c][slot12] (k=slot, 9..11 pad)
#define OFF_SB    13824                // u64[10] bias pairs
#define OFF_SBF   13904                // u32[2304] B fragments [k][term][nt][lane][reg]
#define OFF_STAGE 23120                // 4 warps x 64 px x 48B A-staging
#define OFF_TILE  35408                // x tile 22*22*20*4
#define SMEM_BYTES 74128

typedef unsigned long long u64;

__device__ float g_pre [N_*64*HW];
__device__ float g_stat[2*N_*64];

// ---- packed f32x2 helpers ----
__device__ __forceinline__ u64 pack2(float lo, float hi) {
    u64 r; asm("mov.b64 %0,{%1,%2};" : "=l"(r) : "f"(lo), "f"(hi)); return r;
}
__device__ __forceinline__ float2 unpack2(u64 v) {
    float2 r; asm("mov.b64 {%0,%1},%2;" : "=f"(r.x), "=f"(r.y) : "l"(v)); return r;
}
__device__ __forceinline__ void ffma2(u64 &d, u64 a, u64 b) {
    asm("fma.rn.f32x2 %0,%1,%2,%0;" : "+l"(d) : "l"(a), "l"(b));
}
__device__ __forceinline__ u64 mul2(u64 a, u64 b) {
    u64 r; asm("mul.rn.f32x2 %0,%1,%2;" : "=l"(r) : "l"(a), "l"(b)); return r;
}
__device__ __forceinline__ u64 dup2(float v) { return pack2(v, v); }

// fp32 pair -> hi bf16x2 word + lo residual bf16x2 word (element0 in low bits)
__device__ __forceinline__ void cvt_split(u64 vp, uint32_t &hw, uint32_t &lw) {
    float2 v = unpack2(vp);
    uint32_t h;
    asm("cvt.rn.bf16x2.f32 %0, %1, %2;" : "=r"(h) : "f"(v.y), "f"(v.x));
    const float h0 = __uint_as_float(h << 16);
    const float h1 = __uint_as_float(h & 0xffff0000u);
    const float l0 = v.x - h0, l1 = v.y - h1;
    uint32_t l;
    asm("cvt.rn.bf16x2.f32 %0, %1, %2;" : "=r"(l) : "f"(l1), "f"(l0));
    hw = h; lw = l;
}

__device__ __forceinline__ void bf16split(float w, uint32_t &hi, uint32_t &lo) {
    const uint32_t b = __float_as_uint(w);
    hi = (b + 0x7fffu + ((b >> 16) & 1u)) >> 16;
    const float r = w - __uint_as_float(hi << 16);
    const uint32_t b2 = __float_as_uint(r);
    lo = (b2 + 0x7fffu + ((b2 >> 16) & 1u)) >> 16;
}

// legacy tensor-core path (no sm_103a features needed)
__device__ __forceinline__ void ldsm4(uint32_t* r, uint32_t addr) {
    asm volatile("ldmatrix.sync.aligned.m8n8.x4.shared.b16 {%0,%1,%2,%3}, [%4];"
        : "=r"(r[0]), "=r"(r[1]), "=r"(r[2]), "=r"(r[3]) : "r"(addr));
}
__device__ __forceinline__ void mma16816(float* d, const uint32_t* a, uint2 b) {
    asm volatile("mma.sync.aligned.m16n8k16.row.col.f32.bf16.bf16.f32 "
        "{%0,%1,%2,%3}, {%4,%5,%6,%7}, {%8,%9}, {%0,%1,%2,%3};"
        : "+f"(d[0]), "+f"(d[1]), "+f"(d[2]), "+f"(d[3])
        : "r"(a[0]), "r"(a[1]), "r"(a[2]), "r"(a[3]), "r"(b.x), "r"(b.y));
}

__global__ __launch_bounds__(THREADS) void fused_kernel(const float* __restrict__ x,
                                                        const float* __restrict__ w_off,
                                                        const float* __restrict__ b_off,
                                                        const float* __restrict__ w_dc) {
    extern __shared__ __align__(16) char smem_raw[];
    u64*      swc   = reinterpret_cast<u64*>(smem_raw);
    u64*      sb    = reinterpret_cast<u64*>(smem_raw + OFF_SB);
    uint32_t* sbf   = reinterpret_cast<uint32_t*>(smem_raw + OFF_SBF);
    float*    tile  = reinterpret_cast<float*>(smem_raw + OFF_TILE);

    const int tid = threadIdx.x;
    const int lane = tid & 31, warp = tid >> 5;
    const int bx = blockIdx.x, g = blockIdx.y, n = blockIdx.z;
    const int ty0 = (bx >> 2) * TH, tx0 = (bx & 3) * TW;
    const float* xg = x + ((size_t)(n * 64 + g * 16)) * HW;
    const uint32_t smem_base = (uint32_t)__cvta_generic_to_shared(smem_raw);

    // conv weights (f32x2 pairs), slot = k (9..11 zero)
    for (int i = tid; i < SWC_U64; i += THREADS) {
        const int slot = i % 12, c = (i / 12) % 16, pos = i / 192;
        u64 v = 0ULL;
        if (slot < 9)
            v = pack2(w_off[((g*18 + 2*slot)   * 16 + c) * 9 + pos],
                      w_off[((g*18 + 2*slot+1) * 16 + c) * 9 + pos]);
        swc[i] = v;
    }
    if (tid < 10)
        sb[tid] = (tid < 9) ? pack2(b_off[g*18 + 2*tid], b_off[g*18 + 2*tid + 1]) : 0ULL;

    // einsum B fragments in m16n8k16 ownership layout: [k][term][nt][lane][reg]
    for (int i = tid; i < 2304; i += THREADS) {
        const int reg  = i & 1;
        const int ln   = (i >> 1) & 31;
        const int nt   = (i >> 6) & 1;
        const int term = (i >> 7) & 1;
        const int k    = i >> 8;
        const int gidp = ln >> 2, tigp = ln & 3;
        const int o  = nt * 8 + gidp;
        const int c0 = tigp * 2 + reg * 8;
        uint32_t h0, l0, h1, l1;
        bf16split(w_dc[((g*16 + o) * 16 + c0    ) * 9 + k], h0, l0);
        bf16split(w_dc[((g*16 + o) * 16 + c0 + 1) * 9 + k], h1, l1);
        sbf[i] = (term == 0) ? (h0 | (h1 << 16)) : (l0 | (l1 << 16));
    }

    // x tile (zero halo = conv boundary skip)
    for (int sp = tid; sp < SH * SW; sp += THREADS) {
        const int gy = ty0 - HALO + sp / SW;
        const int gx = tx0 - HALO + sp % SW;
        const bool in = ((unsigned)gy < 64u) && ((unsigned)gx < 64u);
        const int gp = gy * 64 + gx;
        #pragma unroll
        for (int c = 0; c < 16; c++)
            tile[sp * PSTR + c] = in ? xg[(size_t)c * HW + gp] : 0.f;
    }
    __syncthreads();

    const int rloc  = (tid >> 4) * PPT;      // 2 adjacent pixel rows
    const int lanex = tid & 15;

    // ---- Phase A: offset conv, all 9 taps, accumulate in registers ----
    u64 ao[PPT][9];
    #pragma unroll
    for (int pix = 0; pix < PPT; pix++)
        #pragma unroll
        for (int k = 0; k < 9; k++) ao[pix][k] = sb[k];

    #pragma unroll 1
    for (int j = 0; j < 4; j++) {
        #pragma unroll 1
        for (int cx = 0; cx < 3; cx++) {
            float4 R[4];
            #pragma unroll
            for (int ry = 0; ry < 4; ry++)
                R[ry] = *reinterpret_cast<const float4*>(
                    tile + ((rloc + HALO - 1 + ry) * SW + (lanex + HALO - 1 + cx)) * PSTR + 4*j);
            #pragma unroll
            for (int posr = 0; posr < 3; posr++) {
                const int pos = posr * 3 + cx;
                #pragma unroll
                for (int q = 0; q < 4; q++) {
                    const u64* wb = swc + (pos * 16 + 4*j + q) * 12;
                    const ulonglong2 wA = *reinterpret_cast<const ulonglong2*>(wb);
                    const ulonglong2 wB = *reinterpret_cast<const ulonglong2*>(wb + 2);
                    const ulonglong2 wC = *reinterpret_cast<const ulonglong2*>(wb + 4);
                    const ulonglong2 wD = *reinterpret_cast<const ulonglong2*>(wb + 6);
                    const u64 w8 = wb[8];
                    #pragma unroll
                    for (int pix = 0; pix < PPT; pix++) {
                        const float4 X = R[pix + posr];
                        const float xv = (q==0)?X.x:(q==1)?X.y:(q==2)?X.z:X.w;
                        const u64 xd = dup2(xv);
                        ffma2(ao[pix][0], wA.x, xd); ffma2(ao[pix][1], wA.y, xd);
                        ffma2(ao[pix][2], wB.x, xd); ffma2(ao[pix][3], wB.y, xd);
                        ffma2(ao[pix][4], wC.x, xd); ffma2(ao[pix][5], wC.y, xd);
                        ffma2(ao[pix][6], wD.x, xd); ffma2(ao[pix][7], wD.y, xd);
                        ffma2(ao[pix][8], w8,   xd);
                    }
                }
            }
        }
    }
    // park offsets in local mem (dynamic k access below); registers stay clean
    u64 ao_mem[PPT][9];
    #pragma unroll
    for (int pix = 0; pix < PPT; pix++)
        #pragma unroll
        for (int k = 0; k < 9; k++) ao_mem[pix][k] = ao[pix][k];

    // ---- Phase B: per tap: sample -> split bf16 -> stage -> ldmatrix -> mma ----
    float acc[4][2][4];
    #pragma unroll
    for (int mt = 0; mt < 4; mt++)
        #pragma unroll
        for (int nt = 0; nt < 2; nt++)
            #pragma unroll
            for (int r = 0; r < 4; r++) acc[mt][nt][r] = 0.f;

    const int oy = ty0 - HALO, ox = tx0 - HALO;
    const uint32_t stage_base = smem_base + OFF_STAGE + warp * 3072;
    const uint32_t lmbase = stage_base + (lane & 15) * 48 + ((lane >> 4) & 1) * 16;

    #pragma unroll 1
    for (int k = 0; k < 9; k++) {
        const int kdy = k / 3 - 1, kdx = k % 3 - 1;
        uint32_t hiw[PPT][8], low[PPT][8];
        #pragma unroll
        for (int pix = 0; pix < PPT; pix++) {
            const float2 off = unpack2(ao_mem[pix][k]);
            const int hg = ty0 + rloc + pix;
            const int wg = tx0 + lanex;
            const float py = (float)(hg + kdy) + off.x;
            const float px = (float)(wg + kdx) + off.y;
            const float y0f = floorf(py), x0f = floorf(px);
            const float fy = py - y0f, fx = px - x0f;
            const int y0 = (int)y0f, x0 = (int)x0f;
            const bool vy0 = (y0 >= 0)  && (y0 < 64);
            const bool vy1 = (y0 >= -1) && (y0 < 63);
            const bool vx0 = (x0 >= 0)  && (x0 < 64);
            const bool vx1 = (x0 >= -1) && (x0 < 63);
            const u64 w00 = dup2((1.f-fy)*(1.f-fx) * ((vy0&&vx0)?1.f:0.f));
            const u64 w01 = dup2((1.f-fy)*fx       * ((vy0&&vx1)?1.f:0.f));
            const u64 w10 = dup2(fy*(1.f-fx)       * ((vy1&&vx0)?1.f:0.f));
            const u64 w11 = dup2(fy*fx             * ((vy1&&vx1)?1.f:0.f));
            const int yc0 = min(max(y0,0),63), yc1 = min(max(y0+1,0),63);
            const int xc0 = min(max(x0,0),63), xc1 = min(max(x0+1,0),63);
            const int t0y = yc0-oy, t1y = yc1-oy, t0x = xc0-ox, t1x = xc1-ox;
            const bool win = (t0y>=0)&&(t1y<SH)&&(t0x>=0)&&(t1x<SW);
            int c0i, c1i, c2i, c3i;
            if (win) {
                c0i=(t0y*SW+t0x)*PSTR; c1i=(t0y*SW+t1x)*PSTR;
                c2i=(t1y*SW+t0x)*PSTR; c3i=(t1y*SW+t1x)*PSTR;
            } else {
                c0i=yc0*64+xc0; c1i=yc0*64+xc1; c2i=yc1*64+xc0; c3i=yc1*64+xc1;
            }
            #pragma unroll
            for (int j = 0; j < 4; j++) {
                ulonglong2 A2, B2, C2, D2;
                if (win) {
                    A2 = *reinterpret_cast<const ulonglong2*>(tile + c0i + 4*j);
                    B2 = *reinterpret_cast<const ulonglong2*>(tile + c1i + 4*j);
                    C2 = *reinterpret_cast<const ulonglong2*>(tile + c2i + 4*j);
                    D2 = *reinterpret_cast<const ulonglong2*>(tile + c3i + 4*j);
                } else {
                    const float* xq = xg + (size_t)(4*j) * HW;
                    A2.x = pack2(xq[c0i], xq[HW+c0i]); A2.y = pack2(xq[2*HW+c0i], xq[3*HW+c0i]);
                    B2.x = pack2(xq[c1i], xq[HW+c1i]); B2.y = pack2(xq[2*HW+c1i], xq[3*HW+c1i]);
                    C2.x = pack2(xq[c2i], xq[HW+c2i]); C2.y = pack2(xq[2*HW+c2i], xq[3*HW+c2i]);
                    D2.x = pack2(xq[c3i], xq[HW+c3i]); D2.y = pack2(xq[2*HW+c3i], xq[3*HW+c3i]);
                }
                u64 v01 = mul2(w00, A2.x);
                ffma2(v01, w01, B2.x); ffma2(v01, w10, C2.x); ffma2(v01, w11, D2.x);
                u64 v23 = mul2(w00, A2.y);
                ffma2(v23, w01, B2.y); ffma2(v23, w10, C2.y); ffma2(v23, w11, D2.y);
                cvt_split(v01, hiw[pix][2*j],   low[pix][2*j]);
                cvt_split(v23, hiw[pix][2*j+1], low[pix][2*j+1]);
            }
        }

        // B fragments for this tap
        const uint2 bh0 = *reinterpret_cast<const uint2*>(sbf + ((k*2+0)*2+0)*64 + lane*2);
        const uint2 bh1 = *reinterpret_cast<const uint2*>(sbf + ((k*2+0)*2+1)*64 + lane*2);
        const uint2 bl0 = *reinterpret_cast<const uint2*>(sbf + ((k*2+1)*2+0)*64 + lane*2);
        const uint2 bl1 = *reinterpret_cast<const uint2*>(sbf + ((k*2+1)*2+1)*64 + lane*2);

        // stage A_hi, mma with (wh, wl)
        #pragma unroll
        for (int pix = 0; pix < PPT; pix++) {
            const int pxidx = (((tid >> 4) & 1) * PPT + pix) * 16 + lanex;
            uint4* dst = reinterpret_cast<uint4*>(smem_raw + OFF_STAGE + warp*3072 + pxidx*48);
            dst[0] = make_uint4(hiw[pix][0], hiw[pix][1], hiw[pix][2], hiw[pix][3]);
            dst[1] = make_uint4(hiw[pix][4], hiw[pix][5], hiw[pix][6], hiw[pix][7]);
        }
        __syncwarp();
        #pragma unroll
        for (int mt = 0; mt < 4; mt++) {
            uint32_t a[4];
            ldsm4(a, lmbase + mt * 16 * 48);
            mma16816(acc[mt][0], a, bh0);
            mma16816(acc[mt][1], a, bh1);
            mma16816(acc[mt][0], a, bl0);
            mma16816(acc[mt][1], a, bl1);
        }
        __syncwarp();

        // stage A_lo, mma with wh
        #pragma unroll
        for (int pix = 0; pix < PPT; pix++) {
            const int pxidx = (((tid >> 4) & 1) * PPT + pix) * 16 + lanex;
            uint4* dst = reinterpret_cast<uint4*>(smem_raw + OFF_STAGE + warp*3072 + pxidx*48);
            dst[0] = make_uint4(low[pix][0], low[pix][1], low[pix][2], low[pix][3]);
            dst[1] = make_uint4(low[pix][4], low[pix][5], low[pix][6], low[pix][7]);
        }
        __syncwarp();
        #pragma unroll
        for (int mt = 0; mt < 4; mt++) {
            uint32_t a[4];
            ldsm4(a, lmbase + mt * 16 * 48);
            mma16816(acc[mt][0], a, bh0);
            mma16816(acc[mt][1], a, bh1);
        }
        __syncwarp();
    }

    // ---- writeback from D fragments ----
    const int gid = lane >> 2, tig = lane & 3;
    #pragma unroll
    for (int mt = 0; mt < 4; mt++) {
        const int row = ty0 + warp * 4 + mt;
        #pragma unroll
        for (int nt = 0; nt < 2; nt++) {
            const int o = g * 16 + nt * 8 + 2 * tig;
            float* base = g_pre + (size_t)(n * 64 + o) * HW + row * 64 + tx0;
            base[gid]          = acc[mt][nt][0];
            base[HW + gid]     = acc[mt][nt][1];
            base[gid + 8]      = acc[mt][nt][2];
            base[HW + gid + 8] = acc[mt][nt][3];
        }
    }
}

// Reduce g_pre plane -> mean & rsqrt(var) per (n, oc)
__global__ void stats_kernel() {
    __shared__ float sh[8];
    const int i = blockIdx.x;                  // (n*64 + oc)
    const float* p = g_pre + (size_t)i * HW;
    float s = 0.f, q = 0.f;
    for (int t = threadIdx.x; t < HW / 4; t += 128) {
        const float4 v = reinterpret_cast<const float4*>(p)[t];
        s += (v.x + v.y) + (v.z + v.w);
        q += v.x*v.x + v.y*v.y + v.z*v.z + v.w*v.w;
    }
    #pragma unroll
    for (int d = 16; d; d >>= 1) {
        s += __shfl_xor_sync(0xffffffffu, s, d);
        q += __shfl_xor_sync(0xffffffffu, q, d);
    }
    const int w = threadIdx.x >> 5;
    if ((threadIdx.x & 31) == 0) { sh[w] = s; sh[4 + w] = q; }
    __syncthreads();
    if (threadIdx.x == 0) {
        s = sh[0] + sh[1] + sh[2] + sh[3];
        q = sh[4] + sh[5] + sh[6] + sh[7];
        const float mean = s * (1.f / HW);
        const float var  = q * (1.f / HW) - mean * mean;
        g_stat[i]           = mean;
        g_stat[N_*64 + i]   = rsqrtf(var + 1e-5f);
    }
}

// Normalize + exact GELU + transposed store
__global__ void norm_gelu_kernel(float* __restrict__ out) {
    const int oc = blockIdx.y;
    const int n  = blockIdx.z;
    const float mean = g_stat[n*64 + oc];
    const float inv  = g_stat[N_*64 + n*64 + oc];

    const int p4 = blockIdx.x * blockDim.x + threadIdx.x;
    const float4 v = reinterpret_cast<const float4*>(g_pre + ((size_t)(n*64 + oc)) * HW)[p4];
    float4 r;
    { const float a = (v.x-mean)*inv; r.x = 0.5f*a*(1.f+erff(a*0.7071067811865475f)); }
    { const float a = (v.y-mean)*inv; r.y = 0.5f*a*(1.f+erff(a*0.7071067811865475f)); }
    { const float a = (v.z-mean)*inv; r.z = 0.5f*a*(1.f+erff(a*0.7071067811865475f)); }
    { const float a = (v.w-mean)*inv; r.w = 0.5f*a*(1.f+erff(a*0.7071067811865475f)); }

    const int b = n >> 3, d = n & 7;
    reinterpret_cast<float4*>(out + ((size_t)((b*64 + oc)*8 + d)) * HW)[p4] = r;
}

extern "C" void kernel_launch(void* const* d_in, const int* in_sizes, int n_in,
                              void* d_out, int out_size) {
    const float* x     = (const float*)d_in[0];
    const float* w_off = (const float*)d_in[1];
    const float* b_off = (const float*)d_in[2];
    const float* w_dc  = (const float*)d_in[3];
    // d_in[4] = b_dc: cancels exactly under per-channel mean subtraction.
    float* out = (float*)d_out;

    cudaFuncSetAttribute(fused_kernel,
                         cudaFuncAttributeMaxDynamicSharedMemorySize, SMEM_BYTES);

    fused_kernel<<<dim3(16, G_, N_), THREADS, SMEM_BYTES>>>(x, w_off, b_off, w_dc);
    stats_kernel<<<N_ * 64, 128>>>();
    norm_gelu_kernel<<<dim3(HW / 1024, 64, N_), 256>>>(out);
}